// round 8
// baseline (speedup 1.0000x reference)
#include <cuda_runtime.h>
#include <cuda_bf16.h>
#include <cstdint>

#define NN 100000
#define NE 3200000
#define NG 256
#define NF 64

// -------- scratch (no allocations allowed) --------
__device__ float  g_deg[NN];
__device__ float  g_dinv[NN];
__device__ float  g_p[NN];                  // x * dinv
__device__ float  g_a[NN];                  // layer-1 aggregate
__device__ int    g_icnt[NN];               // in-degree histogram
__device__ int    g_off[NN];                // CSR offsets (exclusive scan)
__device__ int    g_cur[NN];                // placement cursors
__device__ unsigned long long g_epack[NE];  // dst-sorted edges: (w<<32)|r
__device__ float4 g_s[NN * 16];             // s1 = (h1 @ W2) * dinv  [N,64]
__device__ float  g_gsum[NG * NF];
__device__ float  g_gcnt[NG];

__device__ __forceinline__ float gelu_t(float x) {
    const float c = 0.7978845608028654f;
    float t = tanhf(c * (x + 0.044715f * x * x * x));
    return 0.5f * x * (1.0f + t);
}

__device__ __forceinline__ void red_add_v4(float* addr, float a, float b, float c, float d) {
    asm volatile("red.global.add.v4.f32 [%0], {%1,%2,%3,%4};"
                 :: "l"(addr), "f"(a), "f"(b), "f"(c), "f"(d)
                 : "memory");
}

// K0: init deg=1 (self loop), zero histogram + pool buffers
__global__ void k0_init() {
    int i = blockIdx.x * blockDim.x + threadIdx.x;
    if (i < NN) { g_deg[i] = 1.0f; g_icnt[i] = 0; }
    if (i < NG * NF) g_gsum[i] = 0.0f;
    if (i < NG) g_gcnt[i] = 0.0f;
}

// K1: fused histogram + weighted degree
__global__ void __launch_bounds__(256) k1_histdeg(const int* __restrict__ ei,
                                                  const float* __restrict__ ew) {
    int e = blockIdx.x * blockDim.x + threadIdx.x;
    if (e >= NE) return;
    int c = __ldg(&ei[NE + e]);
    atomicAdd(&g_icnt[c], 1);
    atomicAdd(&g_deg[c], __ldg(&ew[e]));
}

// K2: dinv = rsqrt(deg); p = x*dinv
__global__ void k2_dinv(const float* __restrict__ x) {
    int i = blockIdx.x * blockDim.x + threadIdx.x;
    if (i >= NN) return;
    float d = rsqrtf(g_deg[i]);
    g_dinv[i] = d;
    g_p[i] = x[i] * d;
}

// KS: single-block exclusive scan of g_icnt -> g_off, init g_cur
__global__ void __launch_bounds__(1024) k_scan() {
    __shared__ int sh[1024];
    const int CH = (NN + 1023) / 1024;   // 98
    int tid = threadIdx.x;
    int base = tid * CH;
    int sum = 0;
    #pragma unroll 4
    for (int i = 0; i < CH; i++) {
        int idx = base + i;
        if (idx < NN) sum += g_icnt[idx];
    }
    sh[tid] = sum;
    __syncthreads();
    // Hillis-Steele inclusive scan
    for (int d = 1; d < 1024; d <<= 1) {
        int v = (tid >= d) ? sh[tid - d] : 0;
        __syncthreads();
        sh[tid] += v;
        __syncthreads();
    }
    int run = (tid == 0) ? 0 : sh[tid - 1];
    for (int i = 0; i < CH; i++) {
        int idx = base + i;
        if (idx < NN) {
            g_off[idx] = run;
            g_cur[idx] = run;
            run += g_icnt[idx];
        }
    }
}

// KP: placement scatter — build dst-sorted packed edge list
__global__ void __launch_bounds__(256) k_place(const int* __restrict__ ei,
                                               const float* __restrict__ ew) {
    int e = blockIdx.x * blockDim.x + threadIdx.x;
    if (e >= NE) return;
    int r = __ldg(&ei[e]);
    int c = __ldg(&ei[NE + e]);
    float w = __ldg(&ew[e]);
    int pos = atomicAdd(&g_cur[c], 1);
    g_epack[pos] = ((unsigned long long)__float_as_uint(w) << 32) | (unsigned int)r;
}

// K3b: layer-1 aggregation, gather form (no atomics): a[v] = p[v] + sum p[r]*w
__global__ void __launch_bounds__(256) k3b_gatherA() {
    int v = blockIdx.x * blockDim.x + threadIdx.x;
    if (v >= NN) return;
    float acc = g_p[v];
    int i = g_off[v];
    int end = i + g_icnt[v];
    #pragma unroll 4
    for (; i < end; i++) {
        unsigned long long pk = __ldg(&g_epack[i]);
        int   r = (int)(pk & 0xffffffffu);
        float w = __uint_as_float((unsigned int)(pk >> 32));
        acc = fmaf(w, g_p[r], acc);
    }
    g_a[v] = acc;
}

// K4: h1 = gelu(a*dinv*W1 + b1); s1 = (h1 @ W2)*dinv
__global__ void __launch_bounds__(256) k4_layer1(const float* __restrict__ W1,
                                                 const float* __restrict__ b1,
                                                 const float* __restrict__ W2) {
    __shared__ float W2s[NF * NF];
    __shared__ float hbuf[4][NF];
    int f  = threadIdx.x;
    int ny = threadIdx.y;
    int tid = ny * 64 + f;
    #pragma unroll
    for (int i = 0; i < 16; i++) W2s[tid + i * 256] = W2[tid + i * 256];

    int v = blockIdx.x * 4 + ny;   // NN % 4 == 0
    float ad = g_a[v] * g_dinv[v];
    float h = gelu_t(ad * __ldg(&W1[f]) + __ldg(&b1[f]));
    hbuf[ny][f] = h;
    __syncthreads();

    float t = 0.0f;
    #pragma unroll 8
    for (int k = 0; k < NF; k++) t = fmaf(hbuf[ny][k], W2s[k * NF + f], t);
    ((float*)g_s)[v * NF + f] = t * g_dinv[v];
}

// K5b: layer-2 aggregation (gather, no wide atomics) fused with gelu + pool.
// 16 lanes per node, each lane owns one float4 slice.
__global__ void __launch_bounds__(256) k5b_gatherB(const int* __restrict__ batch,
                                                   const float* __restrict__ b2) {
    int t = blockIdx.x * blockDim.x + threadIdx.x;   // < NN*16
    int v = t >> 4;
    int j = t & 15;
    if (v >= NN) return;

    float4 acc = g_s[v * 16 + j];   // self loop (norm dinv[v]*1*dinv[v] folded: s already *dinv, epilogue *dinv)
    int i = g_off[v];
    int end = i + g_icnt[v];
    #pragma unroll 2
    for (; i < end; i++) {
        unsigned long long pk = __ldg(&g_epack[i]);  // broadcast across the 16 lanes
        int   r = (int)(pk & 0xffffffffu);
        float w = __uint_as_float((unsigned int)(pk >> 32));
        float4 sv = g_s[r * 16 + j];
        acc.x = fmaf(w, sv.x, acc.x);
        acc.y = fmaf(w, sv.y, acc.y);
        acc.z = fmaf(w, sv.z, acc.z);
        acc.w = fmaf(w, sv.w, acc.w);
    }

    float di = g_dinv[v];
    const float4 bj = __ldg(&((const float4*)b2)[j]);
    float h0 = gelu_t(fmaf(acc.x, di, bj.x));
    float h1 = gelu_t(fmaf(acc.y, di, bj.y));
    float h2 = gelu_t(fmaf(acc.z, di, bj.z));
    float h3 = gelu_t(fmaf(acc.w, di, bj.w));

    int g = __ldg(&batch[v]);
    red_add_v4(&g_gsum[g * NF + j * 4], h0, h1, h2, h3);
    if (j == 0) atomicAdd(&g_gcnt[g], 1.0f);
}

// K7: final MLP over 256 graphs
__global__ void __launch_bounds__(256) k7_mlp(const float* __restrict__ fc1W,
                                              const float* __restrict__ fc1b,
                                              const float* __restrict__ fc2W,
                                              const float* __restrict__ fc2b,
                                              float* __restrict__ out) {
    __shared__ float W1s[64 * 32];
    __shared__ float b1s[32];
    __shared__ float W2s[32];
    int g = threadIdx.x;
    #pragma unroll
    for (int i = 0; i < 8; i++) W1s[g + i * 256] = fc1W[g + i * 256];
    if (g < 32) { b1s[g] = fc1b[g]; W2s[g] = fc2W[g]; }
    __syncthreads();

    float cnt = g_gcnt[g];
    float inv = 1.0f / fmaxf(cnt, 1.0f);
    float m[64];
    #pragma unroll
    for (int k = 0; k < 64; k++) m[k] = g_gsum[g * 64 + k] * inv;

    float o = 0.0f;
    #pragma unroll 4
    for (int j = 0; j < 32; j++) {
        float z = b1s[j];
        #pragma unroll 8
        for (int k = 0; k < 64; k++) z = fmaf(m[k], W1s[k * 32 + j], z);
        o = fmaf(gelu_t(z), W2s[j], o);
    }
    out[g] = o + fc2b[0];
}

extern "C" void kernel_launch(void* const* d_in, const int* in_sizes, int n_in,
                              void* d_out, int out_size) {
    const float* x     = (const float*)d_in[0];
    const int*   ei    = (const int*)d_in[1];     // int32 (JAX x64 disabled)
    const float* ew    = (const float*)d_in[2];
    const int*   batch = (const int*)d_in[3];
    const float* W1    = (const float*)d_in[4];
    const float* b1    = (const float*)d_in[5];
    const float* W2    = (const float*)d_in[6];
    const float* b2    = (const float*)d_in[7];
    const float* fc1W  = (const float*)d_in[8];
    const float* fc1b  = (const float*)d_in[9];
    const float* fc2W  = (const float*)d_in[10];
    const float* fc2b  = (const float*)d_in[11];
    float* out = (float*)d_out;

    k0_init<<<(NG * NF + 255) / 256 > (NN + 255) / 256 ? (NG * NF + 255) / 256
                                                       : (NN + 255) / 256, 256>>>();
    k1_histdeg<<<(NE + 255) / 256, 256>>>(ei, ew);
    k2_dinv<<<(NN + 255) / 256, 256>>>(x);
    k_scan<<<1, 1024>>>();
    k_place<<<(NE + 255) / 256, 256>>>(ei, ew);
    k3b_gatherA<<<(NN + 255) / 256, 256>>>();
    k4_layer1<<<NN / 4, dim3(64, 4)>>>(W1, b1, W2);
    k5b_gatherB<<<(NN * 16 + 255) / 256, 256>>>(batch, b2);
    k7_mlp<<<1, 256>>>(fc1W, fc1b, fc2W, fc2b, out);
}

// round 9
// speedup vs baseline: 1.5290x; 1.5290x over previous
#include <cuda_runtime.h>
#include <cuda_bf16.h>
#include <cstdint>

#define NN 100000
#define NE 3200000
#define NG 256
#define NF 64
#define NBLK 98   // ceil(NN/1024)

// -------- scratch (no allocations allowed) --------
__device__ float  g_deg[NN];
__device__ float  g_dinv[NN];
__device__ float  g_p[NN];                  // x * dinv
__device__ float  g_a[NN];                  // layer-1 aggregate
__device__ int    g_icnt[NN];               // in-degree histogram
__device__ int    g_off[NN];                // CSR offsets (exclusive scan)
__device__ int    g_cur[NN];                // placement cursors
__device__ int    g_bsum[NBLK];             // per-block totals
__device__ int    g_boff[NBLK];             // scanned block offsets
__device__ unsigned long long g_epack[NE];  // dst-sorted edges: (w<<32)|r
__device__ float4 g_s[NN * 16];             // s1 = (h1 @ W2) * dinv  [N,64]
__device__ float  g_gsum[NG * NF];
__device__ float  g_gcnt[NG];

__device__ __forceinline__ float gelu_t(float x) {
    const float c = 0.7978845608028654f;
    float t = tanhf(c * (x + 0.044715f * x * x * x));
    return 0.5f * x * (1.0f + t);
}

__device__ __forceinline__ void red_add_v4(float* addr, float a, float b, float c, float d) {
    asm volatile("red.global.add.v4.f32 [%0], {%1,%2,%3,%4};"
                 :: "l"(addr), "f"(a), "f"(b), "f"(c), "f"(d)
                 : "memory");
}

// K0: init deg=1 (self loop), zero histogram + pool buffers
__global__ void k0_init() {
    int i = blockIdx.x * blockDim.x + threadIdx.x;
    if (i < NN) { g_deg[i] = 1.0f; g_icnt[i] = 0; }
    if (i < NG * NF) g_gsum[i] = 0.0f;
    if (i < NG) g_gcnt[i] = 0.0f;
}

// K1: fused histogram + weighted degree
__global__ void __launch_bounds__(256) k1_histdeg(const int* __restrict__ ei,
                                                  const float* __restrict__ ew) {
    int e = blockIdx.x * blockDim.x + threadIdx.x;
    if (e >= NE) return;
    int c = __ldg(&ei[NE + e]);
    atomicAdd(&g_icnt[c], 1);
    atomicAdd(&g_deg[c], __ldg(&ew[e]));
}

// K2: dinv = rsqrt(deg); p = x*dinv
__global__ void k2_dinv(const float* __restrict__ x) {
    int i = blockIdx.x * blockDim.x + threadIdx.x;
    if (i >= NN) return;
    float d = rsqrtf(g_deg[i]);
    g_dinv[i] = d;
    g_p[i] = x[i] * d;
}

// --- hierarchical exclusive scan of g_icnt ---
// SA: per-block scan (1024 threads), partial exclusive into g_off, total into g_bsum
__global__ void __launch_bounds__(1024) k_scanA() {
    __shared__ int wsum[32];
    int t = threadIdx.x, b = blockIdx.x;
    int i = b * 1024 + t;
    int v = (i < NN) ? g_icnt[i] : 0;
    int lane = t & 31, wid = t >> 5;
    int s = v;
    #pragma unroll
    for (int d = 1; d < 32; d <<= 1) {
        int u = __shfl_up_sync(0xffffffffu, s, d);
        if (lane >= d) s += u;
    }
    if (lane == 31) wsum[wid] = s;
    __syncthreads();
    if (wid == 0) {
        int ws = wsum[lane];
        #pragma unroll
        for (int d = 1; d < 32; d <<= 1) {
            int u = __shfl_up_sync(0xffffffffu, ws, d);
            if (lane >= d) ws += u;
        }
        wsum[lane] = ws;
    }
    __syncthreads();
    int excl = s - v + (wid > 0 ? wsum[wid - 1] : 0);
    if (i < NN) g_off[i] = excl;
    if (t == 1023) g_bsum[b] = wsum[31];
}

// SB: scan the 98 block totals (1 warp per 32, 128 threads)
__global__ void __launch_bounds__(128) k_scanB() {
    __shared__ int wsum[4];
    int t = threadIdx.x;
    int v = (t < NBLK) ? g_bsum[t] : 0;
    int lane = t & 31, wid = t >> 5;
    int s = v;
    #pragma unroll
    for (int d = 1; d < 32; d <<= 1) {
        int u = __shfl_up_sync(0xffffffffu, s, d);
        if (lane >= d) s += u;
    }
    if (lane == 31) wsum[wid] = s;
    __syncthreads();
    if (wid == 0 && lane < 4) {
        int ws = wsum[lane];
        #pragma unroll
        for (int d = 1; d < 4; d <<= 1) {
            int u = __shfl_up_sync(0x0000000fu, ws, d);
            if (lane >= d) ws += u;
        }
        wsum[lane] = ws;
    }
    __syncthreads();
    int excl = s - v + (wid > 0 ? wsum[wid - 1] : 0);
    if (t < NBLK) g_boff[t] = excl;
}

// SC: add block offsets; init cursors
__global__ void __launch_bounds__(1024) k_scanC() {
    int i = blockIdx.x * 1024 + threadIdx.x;
    if (i >= NN) return;
    int o = g_off[i] + g_boff[blockIdx.x];
    g_off[i] = o;
    g_cur[i] = o;
}

// KP: placement scatter — build dst-sorted packed edge list
__global__ void __launch_bounds__(256) k_place(const int* __restrict__ ei,
                                               const float* __restrict__ ew) {
    int e = blockIdx.x * blockDim.x + threadIdx.x;
    if (e >= NE) return;
    int r = __ldg(&ei[e]);
    int c = __ldg(&ei[NE + e]);
    float w = __ldg(&ew[e]);
    int pos = atomicAdd(&g_cur[c], 1);
    g_epack[pos] = ((unsigned long long)__float_as_uint(w) << 32) | (unsigned int)r;
}

// K3b: layer-1 aggregation, gather form: a[v] = p[v] + sum p[r]*w
__global__ void __launch_bounds__(256) k3b_gatherA() {
    int v = blockIdx.x * blockDim.x + threadIdx.x;
    if (v >= NN) return;
    float acc = g_p[v];
    int i = g_off[v];
    int end = i + g_icnt[v];
    #pragma unroll 4
    for (; i < end; i++) {
        unsigned long long pk = __ldg(&g_epack[i]);
        int   r = (int)(pk & 0xffffffffu);
        float w = __uint_as_float((unsigned int)(pk >> 32));
        acc = fmaf(w, g_p[r], acc);
    }
    g_a[v] = acc;
}

// K4: h1 = gelu(a*dinv*W1 + b1); s1 = (h1 @ W2)*dinv
__global__ void __launch_bounds__(256) k4_layer1(const float* __restrict__ W1,
                                                 const float* __restrict__ b1,
                                                 const float* __restrict__ W2) {
    __shared__ float W2s[NF * NF];
    __shared__ float hbuf[4][NF];
    int f  = threadIdx.x;
    int ny = threadIdx.y;
    int tid = ny * 64 + f;
    #pragma unroll
    for (int i = 0; i < 16; i++) W2s[tid + i * 256] = W2[tid + i * 256];

    int v = blockIdx.x * 4 + ny;   // NN % 4 == 0
    float ad = g_a[v] * g_dinv[v];
    float h = gelu_t(ad * __ldg(&W1[f]) + __ldg(&b1[f]));
    hbuf[ny][f] = h;
    __syncthreads();

    float t = 0.0f;
    #pragma unroll 8
    for (int k = 0; k < NF; k++) t = fmaf(hbuf[ny][k], W2s[k * NF + f], t);
    ((float*)g_s)[v * NF + f] = t * g_dinv[v];
}

// K5b: layer-2 gather fused with gelu + pool. 16 lanes per node.
// Edge records are loaded cooperatively (coalesced) and broadcast via shfl
// within the 16-lane group; tail is padded with w=0 so the inner loop is
// fixed-trip and unrollable.
__global__ void __launch_bounds__(256) k5b_gatherB(const int* __restrict__ batch,
                                                   const float* __restrict__ b2) {
    int t = blockIdx.x * blockDim.x + threadIdx.x;   // < NN*16
    int v = t >> 4;
    int j = t & 15;
    if (v >= NN) return;
    int lane = threadIdx.x & 31;
    int gbase = lane & 16;                    // 16-lane group base within warp
    unsigned hm = 0xFFFFu << gbase;           // own half-warp mask

    float4 acc = g_s[v * 16 + j];             // self-loop term
    int i = g_off[v];
    int end = i + g_icnt[v];
    for (; i < end; i += 16) {
        int idx = i + j;
        unsigned long long pk = (idx < end) ? __ldg(&g_epack[idx]) : 0ULL; // w=0 pad
        #pragma unroll
        for (int k = 0; k < 16; k++) {
            unsigned long long pkk = __shfl_sync(hm, pk, gbase + k);
            int   r = (int)(pkk & 0xffffffffu);
            float w = __uint_as_float((unsigned int)(pkk >> 32));
            float4 sv = g_s[r * 16 + j];
            acc.x = fmaf(w, sv.x, acc.x);
            acc.y = fmaf(w, sv.y, acc.y);
            acc.z = fmaf(w, sv.z, acc.z);
            acc.w = fmaf(w, sv.w, acc.w);
        }
    }

    float di = g_dinv[v];
    const float4 bj = __ldg(&((const float4*)b2)[j]);
    float h0 = gelu_t(fmaf(acc.x, di, bj.x));
    float h1 = gelu_t(fmaf(acc.y, di, bj.y));
    float h2 = gelu_t(fmaf(acc.z, di, bj.z));
    float h3 = gelu_t(fmaf(acc.w, di, bj.w));

    int g = __ldg(&batch[v]);
    red_add_v4(&g_gsum[g * NF + j * 4], h0, h1, h2, h3);
    if (j == 0) atomicAdd(&g_gcnt[g], 1.0f);
}

// K7: final MLP over 256 graphs
__global__ void __launch_bounds__(256) k7_mlp(const float* __restrict__ fc1W,
                                              const float* __restrict__ fc1b,
                                              const float* __restrict__ fc2W,
                                              const float* __restrict__ fc2b,
                                              float* __restrict__ out) {
    __shared__ float W1s[64 * 32];
    __shared__ float b1s[32];
    __shared__ float W2s[32];
    int g = threadIdx.x;
    #pragma unroll
    for (int i = 0; i < 8; i++) W1s[g + i * 256] = fc1W[g + i * 256];
    if (g < 32) { b1s[g] = fc1b[g]; W2s[g] = fc2W[g]; }
    __syncthreads();

    float cnt = g_gcnt[g];
    float inv = 1.0f / fmaxf(cnt, 1.0f);
    float m[64];
    #pragma unroll
    for (int k = 0; k < 64; k++) m[k] = g_gsum[g * 64 + k] * inv;

    float o = 0.0f;
    #pragma unroll 4
    for (int j = 0; j < 32; j++) {
        float z = b1s[j];
        #pragma unroll 8
        for (int k = 0; k < 64; k++) z = fmaf(m[k], W1s[k * 32 + j], z);
        o = fmaf(gelu_t(z), W2s[j], o);
    }
    out[g] = o + fc2b[0];
}

extern "C" void kernel_launch(void* const* d_in, const int* in_sizes, int n_in,
                              void* d_out, int out_size) {
    const float* x     = (const float*)d_in[0];
    const int*   ei    = (const int*)d_in[1];     // int32 (JAX x64 disabled)
    const float* ew    = (const float*)d_in[2];
    const int*   batch = (const int*)d_in[3];
    const float* W1    = (const float*)d_in[4];
    const float* b1    = (const float*)d_in[5];
    const float* W2    = (const float*)d_in[6];
    const float* b2    = (const float*)d_in[7];
    const float* fc1W  = (const float*)d_in[8];
    const float* fc1b  = (const float*)d_in[9];
    const float* fc2W  = (const float*)d_in[10];
    const float* fc2b  = (const float*)d_in[11];
    float* out = (float*)d_out;

    k0_init<<<(NG * NF + 255) / 256 > (NN + 255) / 256 ? (NG * NF + 255) / 256
                                                       : (NN + 255) / 256, 256>>>();
    k1_histdeg<<<(NE + 255) / 256, 256>>>(ei, ew);
    k2_dinv<<<(NN + 255) / 256, 256>>>(x);
    k_scanA<<<NBLK, 1024>>>();
    k_scanB<<<1, 128>>>();
    k_scanC<<<NBLK, 1024>>>();
    k_place<<<(NE + 255) / 256, 256>>>(ei, ew);
    k3b_gatherA<<<(NN + 255) / 256, 256>>>();
    k4_layer1<<<NN / 4, dim3(64, 4)>>>(W1, b1, W2);
    k5b_gatherB<<<(NN * 16 + 255) / 256, 256>>>(batch, b2);
    k7_mlp<<<1, 256>>>(fc1W, fc1b, fc2W, fc2b, out);
}